// round 11
// baseline (speedup 1.0000x reference)
#include <cuda_runtime.h>
#include <math.h>

#define NN 50000
#define EE 800000
#define U  128
#define ED 64
#define NDEPTH 4
#define NBLK 196                 /* ceil(NN/256) */
#define NT2 8                    /* 32-edge tiles per edge-score block */
#define ES2_HALF (EE/(32*NT2))   /* 3125 blocks per direction */
#define AGG_HALF ((NN+7)/8)      /* 6250 */

// ---------------- scratch (static device memory) ---------------------------
__device__ float g_h[NN * U];
__device__ float g_hnF[NN * U];
__device__ float g_hnB[NN * U];
__device__ float g_gatF[NN * U];
__device__ float g_gatB[NN * U];
__device__ float g_tmp[NN * U];
__device__ float g_repr[NDEPTH * NN * U];
__device__ float g_z[NDEPTH * NN * U];
__device__ float g_score[2 * EE * 8];      // [dir][CSR pos][head]
__device__ int g_degF[NN], g_degB[NN], g_curF[NN], g_curB[NN];
__device__ int g_rpF[NN + 1], g_rpB[NN + 1];
__device__ int g_srcF[EE], g_srcB[EE], g_posF[EE], g_posB[EE];

// ---------------- packed f32x2 helpers --------------------------------------
__device__ __forceinline__ unsigned long long pk(float x, float y) {
    unsigned long long r;
    asm("mov.b64 %0,{%1,%2};" : "=l"(r) : "f"(x), "f"(y));
    return r;
}
__device__ __forceinline__ void fma2(unsigned long long& d, unsigned long long a,
                                     unsigned long long b) {
    asm("fma.rn.f32x2 %0,%1,%2,%0;" : "+l"(d) : "l"(a), "l"(b));
}
__device__ __forceinline__ float2 upk(unsigned long long v) {
    float2 f;
    asm("mov.b64 {%0,%1},%2;" : "=f"(f.x), "=f"(f.y) : "l"(v));
    return f;
}

// ---------------- CSR build --------------------------------------------------
// NOTE: deg/cur arrays must be zero on entry. Statics are zero-initialized at
// module load, and k_zero_counts runs at the TAIL of every call, restoring the
// invariant for the next call/replay (deterministic: same work every call).
__global__ void k_zero_counts() {
    int i = blockIdx.x * 256 + threadIdx.x;
    if (i < NN) { g_degF[i] = 0; g_degB[i] = 0; g_curF[i] = 0; g_curB[i] = 0; }
}
__global__ void k_count(const int2* __restrict__ ei) {
    int e = blockIdx.x * 256 + threadIdx.x;
    int2 t = ei[e];
    atomicAdd(&g_degF[t.x], 1);
    atomicAdd(&g_degB[t.y], 1);
}
// single-block exclusive scan of BOTH degree arrays -> rowptrs (1024 threads)
__global__ __launch_bounds__(1024) void k_scan_both() {
    __shared__ int warpF[32], warpB[32];
    const int CH = (NN + 1023) / 1024;     // 49
    int tid = threadIdx.x;
    int start = tid * CH;
    int end = start + CH; if (end > NN) end = NN;
    int sF = 0, sB = 0;
    for (int i = start; i < end; i++) { sF += g_degF[i]; sB += g_degB[i]; }
    int lane = tid & 31, wid = tid >> 5;
    int vF = sF, vB = sB;
    #pragma unroll
    for (int o = 1; o < 32; o <<= 1) {
        int tF = __shfl_up_sync(0xffffffffu, vF, o);
        int tB = __shfl_up_sync(0xffffffffu, vB, o);
        if (lane >= o) { vF += tF; vB += tB; }
    }
    if (lane == 31) { warpF[wid] = vF; warpB[wid] = vB; }
    __syncthreads();
    if (wid == 0) {
        int wF = warpF[lane], wB = warpB[lane];
        #pragma unroll
        for (int o = 1; o < 32; o <<= 1) {
            int tF = __shfl_up_sync(0xffffffffu, wF, o);
            int tB = __shfl_up_sync(0xffffffffu, wB, o);
            if (lane >= o) { wF += tF; wB += tB; }
        }
        warpF[lane] = wF; warpB[lane] = wB;
    }
    __syncthreads();
    int exF = vF - sF, exB = vB - sB;
    if (wid) { exF += warpF[wid - 1]; exB += warpB[wid - 1]; }
    int runF = exF, runB = exB;
    for (int i = start; i < end; i++) {
        g_rpF[i] = runF; runF += g_degF[i];
        g_rpB[i] = runB; runB += g_degB[i];
    }
    if (tid == 1023) { g_rpF[NN] = runF; g_rpB[NN] = runB; }
}
__global__ void k_fill(const int2* __restrict__ ei) {
    int e = blockIdx.x * 256 + threadIdx.x;
    int2 t = ei[e];
    int pf = g_rpF[t.x] + atomicAdd(&g_curF[t.x], 1);
    g_srcF[pf] = t.y; g_posF[e] = pf;
    int pb = g_rpB[t.y] + atomicAdd(&g_curB[t.y], 1);
    g_srcB[pb] = t.x; g_posB[e] = pb;
}

// ---------------- GEMM core -------------------------------------------------
__device__ __forceinline__ void gemm_core(
    const float* __restrict__ A, const float* __restrict__ A2,
    const float* __restrict__ B, const float* __restrict__ bias,
    const float* __restrict__ resid, float* __restrict__ C, int M, int mode,
    float* sm)
{
    float* Bs = sm;
    float* As = sm + U * U;
    int tid = threadIdx.x;
    for (int i = tid; i < U * U; i += 128) Bs[i] = B[i];
    int row0 = blockIdx.x * 32;
    for (int i = tid; i < 32 * U; i += 128) {
        int r = i >> 7, c = i & 127;
        int rr = row0 + r;
        float v = 0.0f;
        if (rr < M) {
            v = A[(size_t)rr * U + c];
            if (A2) v += A2[(size_t)rr * U + c];
        }
        As[r * 129 + c] = v;
    }
    __syncthreads();
    int cg = tid & 15, rg = tid >> 4;
    unsigned long long acc[4][4];
    #pragma unroll
    for (int r = 0; r < 4; r++)
        #pragma unroll
        for (int j = 0; j < 4; j++) acc[r][j] = 0ull;
    const float* Bp = Bs + cg * 8;
    const float* Ap = As + rg * 4 * 129;
    #pragma unroll 8
    for (int k = 0; k < U; k++) {
        float4 w0 = *(const float4*)(Bp + k * U);
        float4 w1 = *(const float4*)(Bp + k * U + 4);
        unsigned long long b0 = pk(w0.x, w0.y), b1 = pk(w0.z, w0.w);
        unsigned long long b2 = pk(w1.x, w1.y), b3 = pk(w1.z, w1.w);
        #pragma unroll
        for (int r = 0; r < 4; r++) {
            float a = Ap[r * 129 + k];
            unsigned long long aa = pk(a, a);
            fma2(acc[r][0], aa, b0);
            fma2(acc[r][1], aa, b1);
            fma2(acc[r][2], aa, b2);
            fma2(acc[r][3], aa, b3);
        }
    }
    float bv[8];
    #pragma unroll
    for (int j = 0; j < 8; j++) bv[j] = bias ? bias[cg * 8 + j] : 0.0f;
    #pragma unroll
    for (int r = 0; r < 4; r++) {
        int row = row0 + rg * 4 + r;
        if (row >= M) continue;
        float o[8];
        #pragma unroll
        for (int j = 0; j < 4; j++) {
            float2 f = upk(acc[r][j]);
            o[2 * j] = f.x + bv[2 * j];
            o[2 * j + 1] = f.y + bv[2 * j + 1];
        }
        if (resid) {
            float4 r0v = *(const float4*)(resid + (size_t)row * U + cg * 8);
            float4 r1v = *(const float4*)(resid + (size_t)row * U + cg * 8 + 4);
            o[0] += r0v.x; o[1] += r0v.y; o[2] += r0v.z; o[3] += r0v.w;
            o[4] += r1v.x; o[5] += r1v.y; o[6] += r1v.z; o[7] += r1v.w;
        }
        if (mode & 1) {
            #pragma unroll
            for (int j = 0; j < 8; j++) o[j] = tanhf(o[j]);
        }
        float4 s0 = {o[0], o[1], o[2], o[3]};
        float4 s1 = {o[4], o[5], o[6], o[7]};
        ((float4*)(C + (size_t)row * U + cg * 8))[0] = s0;
        ((float4*)(C + (size_t)row * U + cg * 8))[1] = s1;
    }
}

__global__ __launch_bounds__(128) void k_gemm_hn(
    const float* __restrict__ A, const float* __restrict__ B0,
    const float* __restrict__ B1, float* __restrict__ C0, float* __restrict__ C1,
    int M)
{
    extern __shared__ float sm[];
    const float* B = blockIdx.y ? B1 : B0;
    float* C = blockIdx.y ? C1 : C0;
    gemm_core(A, nullptr, B, nullptr, nullptr, C, M, 0, sm);
}

__global__ __launch_bounds__(128) void k_gemmA(
    const float* __restrict__ A, const float* __restrict__ A2,
    const float* __restrict__ B, const float* __restrict__ bias,
    const float* __restrict__ resid, float* __restrict__ C, int M, int mode,
    long yoff)
{
    extern __shared__ float sm[];
    gemm_core(A + blockIdx.y * yoff, A2, B, bias, resid, C + blockIdx.y * yoff,
              M, mode, sm);
}

// ---------------- edge score: warp=head, lane=edge, broadcast weights -------
// Per 32-edge tile: weight LDS are warp-uniform (broadcast, 1 cyc) instead of
// per-lane-distinct (4 cyc). 8 f32x2 accumulators/thread -> no spills.
__global__ __launch_bounds__(256) void k_edge_score(
    const float* __restrict__ ef,
    const int2* __restrict__ eiF, const int2* __restrict__ eiB,
    const float* __restrict__ WeF, const float* __restrict__ WeB,
    const float* __restrict__ bF, const float* __restrict__ bB,
    const float* __restrict__ attF, const float* __restrict__ attB,
    const int* __restrict__ posF, const int* __restrict__ posB)
{
    __shared__ alignas(16) float We_s[ED * U];   // 32KB
    __shared__ float b_s[U], att_s[U];
    __shared__ float e_s[32 * 65];               // stride 65: conflict-free reads
    int bx = blockIdx.x;
    bool bwd = bx >= ES2_HALF;
    if (bwd) bx -= ES2_HALF;
    const int2* ei   = bwd ? eiB  : eiF;
    const float* We  = bwd ? WeB  : WeF;
    const float* bb  = bwd ? bB   : bF;
    const float* att = bwd ? attB : attF;
    const int* pos   = bwd ? posB : posF;
    const float* hn  = bwd ? g_hnB : g_hnF;
    float* scoreOut  = g_score + (bwd ? (size_t)EE * 8 : 0);

    int tid = threadIdx.x;
    for (int i = tid; i < ED * U; i += 256) We_s[i] = We[i];
    if (tid < U) { b_s[tid] = bb[tid]; att_s[tid] = att[tid]; }
    __syncthreads();

    int w = tid >> 5, lane = tid & 31;
    int col0 = w * 16;
    float attv[16];
    #pragma unroll
    for (int j = 0; j < 16; j++) attv[j] = att_s[col0 + j];
    unsigned long long binit[8];
    #pragma unroll
    for (int j = 0; j < 8; j++)
        binit[j] = pk(b_s[col0 + 2 * j], b_s[col0 + 2 * j + 1]);

    for (int t = 0; t < NT2; t++) {
        int e0 = (bx * NT2 + t) * 32;
        __syncthreads();
        for (int i = tid; i < 32 * ED; i += 256) {
            int edge = i >> 6, k = i & 63;
            e_s[edge * 65 + k] = ef[(size_t)(e0 + edge) * ED + k];
        }
        __syncthreads();
        unsigned long long acc[8];
        #pragma unroll
        for (int j = 0; j < 8; j++) acc[j] = binit[j];
        const float* ep = e_s + lane * 65;
        #pragma unroll 4
        for (int k = 0; k < ED; k++) {
            float a = ep[k];
            unsigned long long aa = pk(a, a);
            const float4* wp = (const float4*)(We_s + k * U + col0);
            float4 w0 = wp[0], w1 = wp[1], w2 = wp[2], w3 = wp[3];
            fma2(acc[0], aa, pk(w0.x, w0.y));
            fma2(acc[1], aa, pk(w0.z, w0.w));
            fma2(acc[2], aa, pk(w1.x, w1.y));
            fma2(acc[3], aa, pk(w1.z, w1.w));
            fma2(acc[4], aa, pk(w2.x, w2.y));
            fma2(acc[5], aa, pk(w2.z, w2.w));
            fma2(acc[6], aa, pk(w3.x, w3.y));
            fma2(acc[7], aa, pk(w3.z, w3.w));
        }
        int e = e0 + lane;
        int2 ts = ei[e];
        const float* ps = hn + (size_t)ts.y * U + col0;   // src
        const float* pt = hn + (size_t)ts.x * U + col0;   // tgt
        float p = 0.0f;
        #pragma unroll
        for (int q = 0; q < 4; q++) {
            float4 hs = *(const float4*)(ps + q * 4);
            float4 ht = *(const float4*)(pt + q * 4);
            float2 f01 = upk(acc[q * 2]);
            float2 f23 = upk(acc[q * 2 + 1]);
            float v0 = hs.x + ht.x + f01.x;
            float v1 = hs.y + ht.y + f01.y;
            float v2 = hs.z + ht.z + f23.x;
            float v3 = hs.w + ht.w + f23.y;
            v0 = fmaxf(v0, 0.2f * v0);
            v1 = fmaxf(v1, 0.2f * v1);
            v2 = fmaxf(v2, 0.2f * v2);
            v3 = fmaxf(v3, 0.2f * v3);
            p += v0 * attv[q * 4] + v1 * attv[q * 4 + 1]
               + v2 * attv[q * 4 + 2] + v3 * attv[q * 4 + 3];
        }
        scoreOut[(size_t)pos[e] * 8 + w] = p;
    }
}

// ---------------- segment softmax + weighted aggregation --------------------
__device__ __forceinline__ float sel8(const float a[8], int h) {
    float r = a[0];
    r = (h == 1) ? a[1] : r; r = (h == 2) ? a[2] : r; r = (h == 3) ? a[3] : r;
    r = (h == 4) ? a[4] : r; r = (h == 5) ? a[5] : r; r = (h == 6) ? a[6] : r;
    r = (h == 7) ? a[7] : r;
    return r;
}
__global__ __launch_bounds__(256) void k_aggregate()
{
    int bx = blockIdx.x;
    bool bwd = bx >= AGG_HALF;
    if (bwd) bx -= AGG_HALF;
    const int* rowptr = bwd ? g_rpB : g_rpF;
    const int* srcarr = bwd ? g_srcB : g_srcF;
    const float* hn   = bwd ? g_hnB : g_hnF;
    float* outb       = bwd ? g_gatB : g_gatF;
    const float* sco  = g_score + (bwd ? (size_t)EE * 8 : 0);

    int n = bx * 8 + (threadIdx.x >> 5);
    int lane = threadIdx.x & 31;
    if (n >= NN) return;
    int r0 = rowptr[n], r1 = rowptr[n + 1];
    int h4 = lane >> 2;
    float m[8];
    #pragma unroll
    for (int h = 0; h < 8; h++) m[h] = -3.0e38f;
    for (int i = r0 + lane; i < r1; i += 32) {
        const float4* sp = (const float4*)(sco + (size_t)i * 8);
        float4 a = sp[0], b = sp[1];
        m[0] = fmaxf(m[0], a.x); m[1] = fmaxf(m[1], a.y);
        m[2] = fmaxf(m[2], a.z); m[3] = fmaxf(m[3], a.w);
        m[4] = fmaxf(m[4], b.x); m[5] = fmaxf(m[5], b.y);
        m[6] = fmaxf(m[6], b.z); m[7] = fmaxf(m[7], b.w);
    }
    #pragma unroll
    for (int off = 16; off; off >>= 1)
        #pragma unroll
        for (int h = 0; h < 8; h++)
            m[h] = fmaxf(m[h], __shfl_xor_sync(0xffffffffu, m[h], off));
    float den[8];
    #pragma unroll
    for (int h = 0; h < 8; h++) den[h] = 0.0f;
    for (int i = r0 + lane; i < r1; i += 32) {
        const float4* sp = (const float4*)(sco + (size_t)i * 8);
        float4 a = sp[0], b = sp[1];
        den[0] += __expf(a.x - m[0]); den[1] += __expf(a.y - m[1]);
        den[2] += __expf(a.z - m[2]); den[3] += __expf(a.w - m[3]);
        den[4] += __expf(b.x - m[4]); den[5] += __expf(b.y - m[5]);
        den[6] += __expf(b.z - m[6]); den[7] += __expf(b.w - m[7]);
    }
    #pragma unroll
    for (int off = 16; off; off >>= 1)
        #pragma unroll
        for (int h = 0; h < 8; h++)
            den[h] += __shfl_xor_sync(0xffffffffu, den[h], off);
    float myinv = 1.0f / (sel8(den, h4) + 1e-9f);
    float mh = sel8(m, h4);
    float4 acc = {0.0f, 0.0f, 0.0f, 0.0f};
    int i = r0;
    for (; i + 2 <= r1; i += 2) {
        int s0 = srcarr[i], s1 = srcarr[i + 1];
        float sc0 = sco[(size_t)i * 8 + h4];
        float sc1 = sco[(size_t)(i + 1) * 8 + h4];
        float4 h0 = *(const float4*)(hn + (size_t)s0 * U + lane * 4);
        float4 h1 = *(const float4*)(hn + (size_t)s1 * U + lane * 4);
        float a0 = __expf(sc0 - mh) * myinv;
        float a1 = __expf(sc1 - mh) * myinv;
        acc.x += a0 * h0.x + a1 * h1.x;
        acc.y += a0 * h0.y + a1 * h1.y;
        acc.z += a0 * h0.z + a1 * h1.z;
        acc.w += a0 * h0.w + a1 * h1.w;
    }
    if (i < r1) {
        int s0 = srcarr[i];
        float sc0 = sco[(size_t)i * 8 + h4];
        float4 h0 = *(const float4*)(hn + (size_t)s0 * U + lane * 4);
        float a0 = __expf(sc0 - mh) * myinv;
        acc.x += a0 * h0.x; acc.y += a0 * h0.y;
        acc.z += a0 * h0.z; acc.w += a0 * h0.w;
    }
    *(float4*)(outb + (size_t)n * U + lane * 4) = acc;
}

// ---------------- dual RMS ---------------------------------------------------
__global__ __launch_bounds__(128) void k_rms_dual(
    const float* __restrict__ X, const float* __restrict__ gm,
    const float* __restrict__ fg, float* __restrict__ Yrep, float* __restrict__ Yh)
{
    __shared__ float red[4];
    int n = blockIdx.x, tid = threadIdx.x;
    float v = X[(size_t)n * U + tid];
    float s = v * v;
    #pragma unroll
    for (int off = 16; off; off >>= 1) s += __shfl_xor_sync(0xffffffffu, s, off);
    if ((tid & 31) == 0) red[tid >> 5] = s;
    __syncthreads();
    float tot = red[0] + red[1] + red[2] + red[3];
    float r1 = rsqrtf(tot * (1.0f / U) + 1e-6f);
    float rep = v * r1 * gm[tid];
    Yrep[(size_t)n * U + tid] = rep;
    if (Yh) {
        __syncthreads();
        float s2 = rep * rep;
        #pragma unroll
        for (int off = 16; off; off >>= 1) s2 += __shfl_xor_sync(0xffffffffu, s2, off);
        if ((tid & 31) == 0) red[tid >> 5] = s2;
        __syncthreads();
        float tot2 = red[0] + red[1] + red[2] + red[3];
        float r2 = rsqrtf(tot2 * (1.0f / U) + 1e-6f);
        Yh[(size_t)n * U + tid] = rep * r2 * fg[tid];
    }
}

// ---------------- depth-attention fusion ------------------------------------
__global__ __launch_bounds__(128) void k_fuse2(
    const float* __restrict__ mw, const float* __restrict__ mwb,
    const float* __restrict__ fg, float* __restrict__ out)
{
    __shared__ float red[4][NDEPTH];
    __shared__ float red2[4];
    int n = blockIdx.x, tid = threadIdx.x;
    float mwv = mw[tid];
    float z[NDEPTH], rep[NDEPTH];
    #pragma unroll
    for (int d = 0; d < NDEPTH; d++) {
        z[d] = g_z[(size_t)d * (NN * U) + (size_t)n * U + tid];
        rep[d] = g_repr[(size_t)d * (NN * U) + (size_t)n * U + tid];
    }
    #pragma unroll
    for (int d = 0; d < NDEPTH; d++) {
        float val = z[d] * mwv;
        #pragma unroll
        for (int off = 16; off; off >>= 1) val += __shfl_xor_sync(0xffffffffu, val, off);
        if ((tid & 31) == 0) red[tid >> 5][d] = val;
    }
    __syncthreads();
    float b0 = mwb[0];
    float sd[NDEPTH], mx = -1e30f;
    #pragma unroll
    for (int d = 0; d < NDEPTH; d++) {
        sd[d] = red[0][d] + red[1][d] + red[2][d] + red[3][d] + b0;
        mx = fmaxf(mx, sd[d]);
    }
    float w[NDEPTH], wsum = 0.0f;
    #pragma unroll
    for (int d = 0; d < NDEPTH; d++) { w[d] = __expf(sd[d] - mx); wsum += w[d]; }
    float inv = 1.0f / wsum;
    float fused = 0.0f;
    #pragma unroll
    for (int d = 0; d < NDEPTH; d++) fused += (w[d] * inv) * rep[d];
    float s2 = fused * fused;
    #pragma unroll
    for (int off = 16; off; off >>= 1) s2 += __shfl_xor_sync(0xffffffffu, s2, off);
    if ((tid & 31) == 0) red2[tid >> 5] = s2;
    __syncthreads();
    float tot = red2[0] + red2[1] + red2[2] + red2[3];
    out[(size_t)n * U + tid] = fused * rsqrtf(tot * (1.0f / U) + 1e-6f) * fg[tid];
}

// ---------------- host driver ----------------------------------------------
extern "C" void kernel_launch(void* const* d_in, const int* in_sizes, int n_in,
                              void* d_out, int out_size)
{
    const float* node_features = (const float*)d_in[0];
    const float* edge_features = (const float*)d_in[1];
    const int*   ei_fwd        = (const int*)d_in[2];
    const int*   ei_bwd        = (const int*)d_in[3];
    const float* Wn_f  = (const float*)d_in[4];
    const float* We_f  = (const float*)d_in[5];
    const float* b_f   = (const float*)d_in[6];
    const float* att_f = (const float*)d_in[7];
    const float* Wn_b  = (const float*)d_in[8];
    const float* We_b  = (const float*)d_in[9];
    const float* b_b   = (const float*)d_in[10];
    const float* att_b = (const float*)d_in[11];
    const float* Wo    = (const float*)d_in[12];
    const float* bo    = (const float*)d_in[13];
    const float* gamma = (const float*)d_in[14];
    const float* mo_W  = (const float*)d_in[15];
    const float* mo_b  = (const float*)d_in[16];
    const float* mow_W = (const float*)d_in[17];
    const float* mow_b = (const float*)d_in[18];
    const float* final_gamma = (const float*)d_in[19];

    float *p_h, *p_hnF, *p_hnB, *p_gatF, *p_gatB, *p_tmp, *p_repr, *p_z;
    int *p_posF, *p_posB;
    cudaGetSymbolAddress((void**)&p_h,    g_h);
    cudaGetSymbolAddress((void**)&p_hnF,  g_hnF);
    cudaGetSymbolAddress((void**)&p_hnB,  g_hnB);
    cudaGetSymbolAddress((void**)&p_gatF, g_gatF);
    cudaGetSymbolAddress((void**)&p_gatB, g_gatB);
    cudaGetSymbolAddress((void**)&p_tmp,  g_tmp);
    cudaGetSymbolAddress((void**)&p_repr, g_repr);
    cudaGetSymbolAddress((void**)&p_z,    g_z);
    cudaGetSymbolAddress((void**)&p_posF, g_posF);
    cudaGetSymbolAddress((void**)&p_posB, g_posB);

    const int GEMM_SMEM = (U * U + 32 * 129) * (int)sizeof(float);   // 82048
    cudaFuncSetAttribute(k_gemm_hn, cudaFuncAttributeMaxDynamicSharedMemorySize, GEMM_SMEM);
    cudaFuncSetAttribute(k_gemmA,   cudaFuncAttributeMaxDynamicSharedMemorySize, GEMM_SMEM);

    const int GEMM_GRID = (NN + 31) / 32;   // 1563

    // --- CSR build (deg/cur zeroed by previous call's tail / initial load) ---
    k_count<<<EE / 256, 256>>>((const int2*)ei_fwd);       // 0
    k_scan_both<<<1, 1024>>>();                            // 1
    k_fill<<<EE / 256, 256>>>((const int2*)ei_fwd);        // 2

    const float* hcur = node_features;
    for (int i = 0; i < NDEPTH; i++) {
        k_gemm_hn<<<dim3(GEMM_GRID, 2), 128, GEMM_SMEM>>>(       // 3 <- profiled
            hcur, Wn_f + i * U * U, Wn_b + i * U * U, p_hnF, p_hnB, NN);
        k_edge_score<<<2 * ES2_HALF, 256>>>(                     // 4
            edge_features, (const int2*)ei_fwd, (const int2*)ei_bwd,
            We_f + i * ED * U, We_b + i * ED * U, b_f + i * U, b_b + i * U,
            att_f + i * U, att_b + i * U, p_posF, p_posB);
        k_aggregate<<<2 * AGG_HALF, 256>>>();                    // 5
        k_gemmA<<<dim3(GEMM_GRID, 1), 128, GEMM_SMEM>>>(         // 6
            p_gatF, p_gatB, Wo + i * U * U, bo + i * U, hcur, p_tmp, NN, 0, 0L);
        k_rms_dual<<<NN, 128>>>(p_tmp, gamma + i * U, final_gamma,
                                p_repr + (size_t)i * NN * U,
                                (i < NDEPTH - 1) ? p_h : nullptr);
        hcur = p_h;
    }

    k_gemmA<<<dim3(GEMM_GRID, NDEPTH), 128, GEMM_SMEM>>>(
        p_repr, nullptr, mo_W, mo_b, nullptr, p_z, NN, 1, (long)NN * U);
    k_fuse2<<<NN, 128>>>(mow_W, mow_b, final_gamma, (float*)d_out);

    // restore deg/cur = 0 invariant for the next call / graph replay
    k_zero_counts<<<NBLK, 256>>>();
}

// round 12
// speedup vs baseline: 1.2683x; 1.2683x over previous
#include <cuda_runtime.h>
#include <math.h>

#define NN 50000
#define EE 800000
#define U  128
#define ED 64
#define NDEPTH 4
#define NBLK 196              /* ceil(NN/256) */
#define ES_HALF (EE/128)      /* 6250 edge-score blocks per direction */
#define AGG_HALF ((NN+7)/8)   /* 6250 */
#define GROWS 64              /* GEMM rows per block */
#define ASTRIDE 132           /* padded A-tile stride (mult of 4, !mult of 32) */

// ---------------- scratch (static device memory) ---------------------------
__device__ float g_h[NN * U];
__device__ float g_hnF[NN * U];
__device__ float g_hnB[NN * U];
__device__ float g_gatF[NN * U];
__device__ float g_gatB[NN * U];
__device__ float g_tmp[NN * U];
__device__ float g_repr[NDEPTH * NN * U];
__device__ float g_z[NDEPTH * NN * U];
__device__ float g_score[2 * EE * 8];      // [dir][CSR pos][head]
__device__ int g_degF[NN], g_degB[NN], g_curF[NN], g_curB[NN];
__device__ int g_rpF[NN + 1], g_rpB[NN + 1];
__device__ int g_srcF[EE], g_srcB[EE], g_posF[EE], g_posB[EE];

// ---------------- packed f32x2 helpers --------------------------------------
__device__ __forceinline__ unsigned long long pk(float x, float y) {
    unsigned long long r;
    asm("mov.b64 %0,{%1,%2};" : "=l"(r) : "f"(x), "f"(y));
    return r;
}
__device__ __forceinline__ void fma2(unsigned long long& d, unsigned long long a,
                                     unsigned long long b) {
    asm("fma.rn.f32x2 %0,%1,%2,%0;" : "+l"(d) : "l"(a), "l"(b));
}
__device__ __forceinline__ float2 upk(unsigned long long v) {
    float2 f;
    asm("mov.b64 {%0,%1},%2;" : "=f"(f.x), "=f"(f.y) : "l"(v));
    return f;
}

// ---------------- CSR build --------------------------------------------------
// deg/cur must be zero on entry: statics start zeroed; k_zero_counts runs at
// the TAIL of every call restoring the invariant (deterministic each call).
__global__ void k_zero_counts() {
    int i = blockIdx.x * 256 + threadIdx.x;
    if (i < NN) { g_degF[i] = 0; g_degB[i] = 0; g_curF[i] = 0; g_curB[i] = 0; }
}
__global__ void k_count(const int2* __restrict__ ei) {
    int e = blockIdx.x * 256 + threadIdx.x;
    int2 t = ei[e];
    atomicAdd(&g_degF[t.x], 1);
    atomicAdd(&g_degB[t.y], 1);
}
__global__ __launch_bounds__(1024) void k_scan_both() {
    __shared__ int warpF[32], warpB[32];
    const int CH = (NN + 1023) / 1024;     // 49
    int tid = threadIdx.x;
    int start = tid * CH;
    int end = start + CH; if (end > NN) end = NN;
    int sF = 0, sB = 0;
    for (int i = start; i < end; i++) { sF += g_degF[i]; sB += g_degB[i]; }
    int lane = tid & 31, wid = tid >> 5;
    int vF = sF, vB = sB;
    #pragma unroll
    for (int o = 1; o < 32; o <<= 1) {
        int tF = __shfl_up_sync(0xffffffffu, vF, o);
        int tB = __shfl_up_sync(0xffffffffu, vB, o);
        if (lane >= o) { vF += tF; vB += tB; }
    }
    if (lane == 31) { warpF[wid] = vF; warpB[wid] = vB; }
    __syncthreads();
    if (wid == 0) {
        int wF = warpF[lane], wB = warpB[lane];
        #pragma unroll
        for (int o = 1; o < 32; o <<= 1) {
            int tF = __shfl_up_sync(0xffffffffu, wF, o);
            int tB = __shfl_up_sync(0xffffffffu, wB, o);
            if (lane >= o) { wF += tF; wB += tB; }
        }
        warpF[lane] = wF; warpB[lane] = wB;
    }
    __syncthreads();
    int exF = vF - sF, exB = vB - sB;
    if (wid) { exF += warpF[wid - 1]; exB += warpB[wid - 1]; }
    int runF = exF, runB = exB;
    for (int i = start; i < end; i++) {
        g_rpF[i] = runF; runF += g_degF[i];
        g_rpB[i] = runB; runB += g_degB[i];
    }
    if (tid == 1023) { g_rpF[NN] = runF; g_rpB[NN] = runB; }
}
__global__ void k_fill(const int2* __restrict__ ei) {
    int e = blockIdx.x * 256 + threadIdx.x;
    int2 t = ei[e];
    int pf = g_rpF[t.x] + atomicAdd(&g_curF[t.x], 1);
    g_srcF[pf] = t.y; g_posF[e] = pf;
    int pb = g_rpB[t.y] + atomicAdd(&g_curB[t.y], 1);
    g_srcB[pb] = t.x; g_posB[e] = pb;
}

// ---------------- GEMM core: 256 thr, 64-row tile, 4x8 f32x2 per thread -----
__device__ __forceinline__ void gemm_core(
    const float* __restrict__ A, const float* __restrict__ A2,
    const float* __restrict__ B, const float* __restrict__ bias,
    const float* __restrict__ resid, float* __restrict__ C, int M, int mode,
    float* sm)
{
    float* Bs = sm;                       // 128*128 floats
    float* As = sm + U * U;               // 64*132 floats
    int tid = threadIdx.x;                // 256
    for (int i = tid; i < U * U; i += 256) Bs[i] = B[i];
    int row0 = blockIdx.x * GROWS;
    for (int i = tid; i < GROWS * 32; i += 256) {
        int r = i >> 5, c4 = i & 31;
        int rr = row0 + r;
        float4 v = {0.0f, 0.0f, 0.0f, 0.0f};
        if (rr < M) {
            v = *(const float4*)(A + (size_t)rr * U + c4 * 4);
            if (A2) {
                float4 v2 = *(const float4*)(A2 + (size_t)rr * U + c4 * 4);
                v.x += v2.x; v.y += v2.y; v.z += v2.z; v.w += v2.w;
            }
        }
        *(float4*)(As + r * ASTRIDE + c4 * 4) = v;
    }
    __syncthreads();
    int cg = tid & 15, rg = tid >> 4;     // cg: 8-col group, rg: 4-row group
    unsigned long long acc[4][4];
    #pragma unroll
    for (int r = 0; r < 4; r++)
        #pragma unroll
        for (int j = 0; j < 4; j++) acc[r][j] = 0ull;
    const float* Bp = Bs + cg * 8;
    const float* Ap = As + rg * 4 * ASTRIDE;
    #pragma unroll 8
    for (int k = 0; k < U; k++) {
        float4 w0 = *(const float4*)(Bp + k * U);
        float4 w1 = *(const float4*)(Bp + k * U + 4);
        unsigned long long b0 = pk(w0.x, w0.y), b1 = pk(w0.z, w0.w);
        unsigned long long b2 = pk(w1.x, w1.y), b3 = pk(w1.z, w1.w);
        #pragma unroll
        for (int r = 0; r < 4; r++) {
            float a = Ap[r * ASTRIDE + k];
            unsigned long long aa = pk(a, a);
            fma2(acc[r][0], aa, b0);
            fma2(acc[r][1], aa, b1);
            fma2(acc[r][2], aa, b2);
            fma2(acc[r][3], aa, b3);
        }
    }
    float bv[8];
    #pragma unroll
    for (int j = 0; j < 8; j++) bv[j] = bias ? bias[cg * 8 + j] : 0.0f;
    #pragma unroll
    for (int r = 0; r < 4; r++) {
        int row = row0 + rg * 4 + r;
        if (row >= M) continue;
        float o[8];
        #pragma unroll
        for (int j = 0; j < 4; j++) {
            float2 f = upk(acc[r][j]);
            o[2 * j] = f.x + bv[2 * j];
            o[2 * j + 1] = f.y + bv[2 * j + 1];
        }
        if (resid) {
            float4 r0v = *(const float4*)(resid + (size_t)row * U + cg * 8);
            float4 r1v = *(const float4*)(resid + (size_t)row * U + cg * 8 + 4);
            o[0] += r0v.x; o[1] += r0v.y; o[2] += r0v.z; o[3] += r0v.w;
            o[4] += r1v.x; o[5] += r1v.y; o[6] += r1v.z; o[7] += r1v.w;
        }
        if (mode & 1) {
            #pragma unroll
            for (int j = 0; j < 8; j++) o[j] = tanhf(o[j]);
        }
        float4 s0 = {o[0], o[1], o[2], o[3]};
        float4 s1 = {o[4], o[5], o[6], o[7]};
        ((float4*)(C + (size_t)row * U + cg * 8))[0] = s0;
        ((float4*)(C + (size_t)row * U + cg * 8))[1] = s1;
    }
}

__global__ __launch_bounds__(256) void k_gemm_hn(
    const float* __restrict__ A, const float* __restrict__ B0,
    const float* __restrict__ B1, float* __restrict__ C0, float* __restrict__ C1,
    int M)
{
    extern __shared__ float sm[];
    const float* B = blockIdx.y ? B1 : B0;
    float* C = blockIdx.y ? C1 : C0;
    gemm_core(A, nullptr, B, nullptr, nullptr, C, M, 0, sm);
}

__global__ __launch_bounds__(256) void k_gemmA(
    const float* __restrict__ A, const float* __restrict__ A2,
    const float* __restrict__ B, const float* __restrict__ bias,
    const float* __restrict__ resid, float* __restrict__ C, int M, int mode,
    long yoff)
{
    extern __shared__ float sm[];
    gemm_core(A + blockIdx.y * yoff, A2, B, bias, resid, C + blockIdx.y * yoff,
              M, mode, sm);
}

// ---------------- edge score: warp-per-edge (R10 proven), both dirs ---------
__global__ __launch_bounds__(256) void k_edge_score(
    const float* __restrict__ ef,
    const int2* __restrict__ eiF, const int2* __restrict__ eiB,
    const float* __restrict__ WeF, const float* __restrict__ WeB,
    const float* __restrict__ bF, const float* __restrict__ bB,
    const float* __restrict__ attF, const float* __restrict__ attB,
    const int* __restrict__ posF, const int* __restrict__ posB)
{
    __shared__ alignas(16) float We_s[ED * U];   // 32KB
    __shared__ float b_s[U], att_s[U];
    int bx = blockIdx.x;
    bool bwd = bx >= ES_HALF;
    if (bwd) bx -= ES_HALF;
    const int2* ei   = bwd ? eiB  : eiF;
    const float* We  = bwd ? WeB  : WeF;
    const float* bb  = bwd ? bB   : bF;
    const float* att = bwd ? attB : attF;
    const int* pos   = bwd ? posB : posF;
    const float* hn  = bwd ? g_hnB : g_hnF;
    float* scoreOut  = g_score + (bwd ? (size_t)EE * 8 : 0);

    int tid = threadIdx.x;
    for (int i = tid; i < ED * U; i += 256) We_s[i] = We[i];
    if (tid < U) { b_s[tid] = bb[tid]; att_s[tid] = att[tid]; }
    __syncthreads();
    int wid = tid >> 5, lane = tid & 31;
    #pragma unroll 1
    for (int it = 0; it < 16; it++) {
        int e = bx * 128 + it * 8 + wid;
        int2 ts = ei[e];
        int tgt = ts.x, src = ts.y;
        float2 ev = ((const float2*)ef)[(size_t)e * 32 + lane];
        float4 hs = *(const float4*)(hn + (size_t)src * U + lane * 4);
        float4 ht = *(const float4*)(hn + (size_t)tgt * U + lane * 4);
        unsigned long long acc01 = pk(b_s[lane * 4], b_s[lane * 4 + 1]);
        unsigned long long acc23 = pk(b_s[lane * 4 + 2], b_s[lane * 4 + 3]);
        #pragma unroll
        for (int k = 0; k < ED; k++) {
            float a = __shfl_sync(0xffffffffu, (k & 1) ? ev.y : ev.x, k >> 1);
            float4 w = *(const float4*)&We_s[k * U + lane * 4];
            unsigned long long aa = pk(a, a);
            fma2(acc01, aa, pk(w.x, w.y));
            fma2(acc23, aa, pk(w.z, w.w));
        }
        float2 f01 = upk(acc01), f23 = upk(acc23);
        float s0 = hs.x + ht.x + f01.x;
        float s1 = hs.y + ht.y + f01.y;
        float s2 = hs.z + ht.z + f23.x;
        float s3 = hs.w + ht.w + f23.y;
        s0 = fmaxf(s0, 0.2f * s0);
        s1 = fmaxf(s1, 0.2f * s1);
        s2 = fmaxf(s2, 0.2f * s2);
        s3 = fmaxf(s3, 0.2f * s3);
        float p = s0 * att_s[lane * 4] + s1 * att_s[lane * 4 + 1]
                + s2 * att_s[lane * 4 + 2] + s3 * att_s[lane * 4 + 3];
        p += __shfl_xor_sync(0xffffffffu, p, 1);
        p += __shfl_xor_sync(0xffffffffu, p, 2);
        if ((lane & 3) == 0) {
            scoreOut[(size_t)pos[e] * 8 + (lane >> 2)] = p;
        }
    }
}

// ---------------- segment softmax + weighted aggregation --------------------
__device__ __forceinline__ float sel8(const float a[8], int h) {
    float r = a[0];
    r = (h == 1) ? a[1] : r; r = (h == 2) ? a[2] : r; r = (h == 3) ? a[3] : r;
    r = (h == 4) ? a[4] : r; r = (h == 5) ? a[5] : r; r = (h == 6) ? a[6] : r;
    r = (h == 7) ? a[7] : r;
    return r;
}
__global__ __launch_bounds__(256) void k_aggregate()
{
    int bx = blockIdx.x;
    bool bwd = bx >= AGG_HALF;
    if (bwd) bx -= AGG_HALF;
    const int* rowptr = bwd ? g_rpB : g_rpF;
    const int* srcarr = bwd ? g_srcB : g_srcF;
    const float* hn   = bwd ? g_hnB : g_hnF;
    float* outb       = bwd ? g_gatB : g_gatF;
    const float* sco  = g_score + (bwd ? (size_t)EE * 8 : 0);

    int n = bx * 8 + (threadIdx.x >> 5);
    int lane = threadIdx.x & 31;
    if (n >= NN) return;
    int r0 = rowptr[n], r1 = rowptr[n + 1];
    int h4 = lane >> 2;
    float m[8];
    #pragma unroll
    for (int h = 0; h < 8; h++) m[h] = -3.0e38f;
    for (int i = r0 + lane; i < r1; i += 32) {
        const float4* sp = (const float4*)(sco + (size_t)i * 8);
        float4 a = sp[0], b = sp[1];
        m[0] = fmaxf(m[0], a.x); m[1] = fmaxf(m[1], a.y);
        m[2] = fmaxf(m[2], a.z); m[3] = fmaxf(m[3], a.w);
        m[4] = fmaxf(m[4], b.x); m[5] = fmaxf(m[5], b.y);
        m[6] = fmaxf(m[6], b.z); m[7] = fmaxf(m[7], b.w);
    }
    #pragma unroll
    for (int off = 16; off; off >>= 1)
        #pragma unroll
        for (int h = 0; h < 8; h++)
            m[h] = fmaxf(m[h], __shfl_xor_sync(0xffffffffu, m[h], off));
    float den[8];
    #pragma unroll
    for (int h = 0; h < 8; h++) den[h] = 0.0f;
    for (int i = r0 + lane; i < r1; i += 32) {
        const float4* sp = (const float4*)(sco + (size_t)i * 8);
        float4 a = sp[0], b = sp[1];
        den[0] += __expf(a.x - m[0]); den[1] += __expf(a.y - m[1]);
        den[2] += __expf(a.z - m[2]); den[3] += __expf(a.w - m[3]);
        den[4] += __expf(b.x - m[4]); den[5] += __expf(b.y - m[5]);
        den[6] += __expf(b.z - m[6]); den[7] += __expf(b.w - m[7]);
    }
    #pragma unroll
    for (int off = 16; off; off >>= 1)
        #pragma unroll
        for (int h = 0; h < 8; h++)
            den[h] += __shfl_xor_sync(0xffffffffu, den[h], off);
    float myinv = 1.0f / (sel8(den, h4) + 1e-9f);
    float mh = sel8(m, h4);
    float4 acc = {0.0f, 0.0f, 0.0f, 0.0f};
    int i = r0;
    for (; i + 2 <= r1; i += 2) {
        int s0 = srcarr[i], s1 = srcarr[i + 1];
        float sc0 = sco[(size_t)i * 8 + h4];
        float sc1 = sco[(size_t)(i + 1) * 8 + h4];
        float4 h0 = *(const float4*)(hn + (size_t)s0 * U + lane * 4);
        float4 h1 = *(const float4*)(hn + (size_t)s1 * U + lane * 4);
        float a0 = __expf(sc0 - mh) * myinv;
        float a1 = __expf(sc1 - mh) * myinv;
        acc.x += a0 * h0.x + a1 * h1.x;
        acc.y += a0 * h0.y + a1 * h1.y;
        acc.z += a0 * h0.z + a1 * h1.z;
        acc.w += a0 * h0.w + a1 * h1.w;
    }
    if (i < r1) {
        int s0 = srcarr[i];
        float sc0 = sco[(size_t)i * 8 + h4];
        float4 h0 = *(const float4*)(hn + (size_t)s0 * U + lane * 4);
        float a0 = __expf(sc0 - mh) * myinv;
        acc.x += a0 * h0.x; acc.y += a0 * h0.y;
        acc.z += a0 * h0.z; acc.w += a0 * h0.w;
    }
    *(float4*)(outb + (size_t)n * U + lane * 4) = acc;
}

// ---------------- dual RMS ---------------------------------------------------
__global__ __launch_bounds__(128) void k_rms_dual(
    const float* __restrict__ X, const float* __restrict__ gm,
    const float* __restrict__ fg, float* __restrict__ Yrep, float* __restrict__ Yh)
{
    __shared__ float red[4];
    int n = blockIdx.x, tid = threadIdx.x;
    float v = X[(size_t)n * U + tid];
    float s = v * v;
    #pragma unroll
    for (int off = 16; off; off >>= 1) s += __shfl_xor_sync(0xffffffffu, s, off);
    if ((tid & 31) == 0) red[tid >> 5] = s;
    __syncthreads();
    float tot = red[0] + red[1] + red[2] + red[3];
    float r1 = rsqrtf(tot * (1.0f / U) + 1e-6f);
    float rep = v * r1 * gm[tid];
    Yrep[(size_t)n * U + tid] = rep;
    if (Yh) {
        __syncthreads();
        float s2 = rep * rep;
        #pragma unroll
        for (int off = 16; off; off >>= 1) s2 += __shfl_xor_sync(0xffffffffu, s2, off);
        if ((tid & 31) == 0) red[tid >> 5] = s2;
        __syncthreads();
        float tot2 = red[0] + red[1] + red[2] + red[3];
        float r2 = rsqrtf(tot2 * (1.0f / U) + 1e-6f);
        Yh[(size_t)n * U + tid] = rep * r2 * fg[tid];
    }
}

// ---------------- depth-attention fusion ------------------------------------
__global__ __launch_bounds__(128) void k_fuse2(
    const float* __restrict__ mw, const float* __restrict__ mwb,
    const float* __restrict__ fg, float* __restrict__ out)
{
    __shared__ float red[4][NDEPTH];
    __shared__ float red2[4];
    int n = blockIdx.x, tid = threadIdx.x;
    float mwv = mw[tid];
    float z[NDEPTH], rep[NDEPTH];
    #pragma unroll
    for (int d = 0; d < NDEPTH; d++) {
        z[d] = g_z[(size_t)d * (NN * U) + (size_t)n * U + tid];
        rep[d] = g_repr[(size_t)d * (NN * U) + (size_t)n * U + tid];
    }
    #pragma unroll
    for (int d = 0; d < NDEPTH; d++) {
        float val = z[d] * mwv;
        #pragma unroll
        for (int off = 16; off; off >>= 1) val += __shfl_xor_sync(0xffffffffu, val, off);
        if ((tid & 31) == 0) red[tid >> 5][d] = val;
    }
    __syncthreads();
    float b0 = mwb[0];
    float sd[NDEPTH], mx = -1e30f;
    #pragma unroll
    for (int d = 0; d < NDEPTH; d++) {
        sd[d] = red[0][d] + red[1][d] + red[2][d] + red[3][d] + b0;
        mx = fmaxf(mx, sd[d]);
    }
    float w[NDEPTH], wsum = 0.0f;
    #pragma unroll
    for (int d = 0; d < NDEPTH; d++) { w[d] = __expf(sd[d] - mx); wsum += w[d]; }
    float inv = 1.0f / wsum;
    float fused = 0.0f;
    #pragma unroll
    for (int d = 0; d < NDEPTH; d++) fused += (w[d] * inv) * rep[d];
    float s2 = fused * fused;
    #pragma unroll
    for (int off = 16; off; off >>= 1) s2 += __shfl_xor_sync(0xffffffffu, s2, off);
    if ((tid & 31) == 0) red2[tid >> 5] = s2;
    __syncthreads();
    float tot = red2[0] + red2[1] + red2[2] + red2[3];
    out[(size_t)n * U + tid] = fused * rsqrtf(tot * (1.0f / U) + 1e-6f) * fg[tid];
}

// ---------------- host driver ----------------------------------------------
extern "C" void kernel_launch(void* const* d_in, const int* in_sizes, int n_in,
                              void* d_out, int out_size)
{
    const float* node_features = (const float*)d_in[0];
    const float* edge_features = (const float*)d_in[1];
    const int*   ei_fwd        = (const int*)d_in[2];
    const int*   ei_bwd        = (const int*)d_in[3];
    const float* Wn_f  = (const float*)d_in[4];
    const float* We_f  = (const float*)d_in[5];
    const float* b_f   = (const float*)d_in[6];
    const float* att_f = (const float*)d_in[7];
    const float* Wn_b  = (const float*)d_in[8];
    const float* We_b  = (const float*)d_in[9];
    const float* b_b   = (const float*)d_in[10];
    const float* att_b = (const float*)d_in[11];
    const float* Wo    = (const float*)d_in[12];
    const float* bo    = (const float*)d_in[13];
    const float* gamma = (const float*)d_in[14];
    const float* mo_W  = (const float*)d_in[15];
    const float* mo_b  = (const float*)d_in[16];
    const float* mow_W = (const float*)d_in[17];
    const float* mow_b = (const float*)d_in[18];
    const float* final_gamma = (const float*)d_in[19];

    float *p_h, *p_hnF, *p_hnB, *p_gatF, *p_gatB, *p_tmp, *p_repr, *p_z;
    int *p_posF, *p_posB;
    cudaGetSymbolAddress((void**)&p_h,    g_h);
    cudaGetSymbolAddress((void**)&p_hnF,  g_hnF);
    cudaGetSymbolAddress((void**)&p_hnB,  g_hnB);
    cudaGetSymbolAddress((void**)&p_gatF, g_gatF);
    cudaGetSymbolAddress((void**)&p_gatB, g_gatB);
    cudaGetSymbolAddress((void**)&p_tmp,  g_tmp);
    cudaGetSymbolAddress((void**)&p_repr, g_repr);
    cudaGetSymbolAddress((void**)&p_z,    g_z);
    cudaGetSymbolAddress((void**)&p_posF, g_posF);
    cudaGetSymbolAddress((void**)&p_posB, g_posB);

    const int GEMM_SMEM = (U * U + GROWS * ASTRIDE) * (int)sizeof(float); // 99328
    cudaFuncSetAttribute(k_gemm_hn, cudaFuncAttributeMaxDynamicSharedMemorySize, GEMM_SMEM);
    cudaFuncSetAttribute(k_gemmA,   cudaFuncAttributeMaxDynamicSharedMemorySize, GEMM_SMEM);

    const int GEMM_GRID = (NN + GROWS - 1) / GROWS;   // 782

    // --- CSR build (deg/cur zeroed by previous call's tail / initial load) ---
    k_count<<<EE / 256, 256>>>((const int2*)ei_fwd);       // 0
    k_scan_both<<<1, 1024>>>();                            // 1
    k_fill<<<EE / 256, 256>>>((const int2*)ei_fwd);        // 2

    const float* hcur = node_features;
    for (int i = 0; i < NDEPTH; i++) {
        k_gemm_hn<<<dim3(GEMM_GRID, 2), 256, GEMM_SMEM>>>(       // 3 <- profiled
            hcur, Wn_f + i * U * U, Wn_b + i * U * U, p_hnF, p_hnB, NN);
        k_edge_score<<<2 * ES_HALF, 256>>>(
            edge_features, (const int2*)ei_fwd, (const int2*)ei_bwd,
            We_f + i * ED * U, We_b + i * ED * U, b_f + i * U, b_b + i * U,
            att_f + i * U, att_b + i * U, p_posF, p_posB);
        k_aggregate<<<2 * AGG_HALF, 256>>>();
        k_gemmA<<<dim3(GEMM_GRID, 1), 256, GEMM_SMEM>>>(
            p_gatF, p_gatB, Wo + i * U * U, bo + i * U, hcur, p_tmp, NN, 0, 0L);
        k_rms_dual<<<NN, 128>>>(p_tmp, gamma + i * U, final_gamma,
                                p_repr + (size_t)i * NN * U,
                                (i < NDEPTH - 1) ? p_h : nullptr);
        hcur = p_h;
    }

    k_gemmA<<<dim3(GEMM_GRID, NDEPTH), 256, GEMM_SMEM>>>(
        p_repr, nullptr, mo_W, mo_b, nullptr, p_z, NN, 1, (long)NN * U);
    k_fuse2<<<NN, 128>>>(mow_W, mow_b, final_gamma, (float*)d_out);

    // restore deg/cur = 0 invariant for the next call / graph replay
    k_zero_counts<<<NBLK, 256>>>();
}

// round 13
// speedup vs baseline: 1.9606x; 1.5459x over previous
#include <cuda_runtime.h>
#include <math.h>

#define NN 50000
#define EE 800000
#define U  128
#define ED 64
#define NDEPTH 4
#define NBLK 196              /* ceil(NN/256) */
#define AGG_HALF ((NN+7)/8)   /* 6250 */
#define GROWS 64              /* GEMM rows per block */
#define ASTRIDE 132           /* padded A-tile stride */
#define NTV3 8                /* 32-edge tiles per edge-score block */
#define ESV3_HALF (EE/(32*NTV3))   /* 3125 blocks per direction */

/* dynamic smem layout for k_edge_score (float offsets) */
#define WE_OFF  0        /* 64*128 = 8192 */
#define B_OFF   8192     /* 128 */
#define ATT_OFF 8320     /* 128 */
#define E_OFF   8448     /* 32*65 = 2080 */
#define EE_OFF  10528    /* 32*132 = 4224 */
#define ES_SMEM_FLOATS 14752
#define ES_SMEM_BYTES  (ES_SMEM_FLOATS * 4)   /* 59008 */

// ---------------- scratch (static device memory) ---------------------------
__device__ float g_h[NN * U];
__device__ float g_hnF[NN * U];
__device__ float g_hnB[NN * U];
__device__ float g_gatF[NN * U];
__device__ float g_gatB[NN * U];
__device__ float g_tmp[NN * U];
__device__ float g_repr[NDEPTH * NN * U];
__device__ float g_z[NDEPTH * NN * U];
__device__ float g_score[2 * EE * 8];      // [dir][edge][head]  (edge-major)
__device__ int g_degF[NN], g_degB[NN], g_curF[NN], g_curB[NN];
__device__ int g_rpF[NN + 1], g_rpB[NN + 1];
__device__ int g_srcF[EE], g_srcB[EE];
__device__ int g_eidF[EE], g_eidB[EE];     // CSR pos -> edge id

// ---------------- packed f32x2 helpers --------------------------------------
__device__ __forceinline__ unsigned long long pk(float x, float y) {
    unsigned long long r;
    asm("mov.b64 %0,{%1,%2};" : "=l"(r) : "f"(x), "f"(y));
    return r;
}
__device__ __forceinline__ void fma2(unsigned long long& d, unsigned long long a,
                                     unsigned long long b) {
    asm("fma.rn.f32x2 %0,%1,%2,%0;" : "+l"(d) : "l"(a), "l"(b));
}
__device__ __forceinline__ float2 upk(unsigned long long v) {
    float2 f;
    asm("mov.b64 {%0,%1},%2;" : "=f"(f.x), "=f"(f.y) : "l"(v));
    return f;
}

// ---------------- CSR build --------------------------------------------------
// deg/cur must be zero on entry: statics start zeroed; k_zero_counts runs at
// the TAIL of every call restoring the invariant (deterministic each call).
__global__ void k_zero_counts() {
    int i = blockIdx.x * 256 + threadIdx.x;
    if (i < NN) { g_degF[i] = 0; g_degB[i] = 0; g_curF[i] = 0; g_curB[i] = 0; }
}
__global__ void k_count(const int2* __restrict__ ei) {
    int e = blockIdx.x * 256 + threadIdx.x;
    int2 t = ei[e];
    atomicAdd(&g_degF[t.x], 1);
    atomicAdd(&g_degB[t.y], 1);
}
__global__ __launch_bounds__(1024) void k_scan_both() {
    __shared__ int warpF[32], warpB[32];
    const int CH = (NN + 1023) / 1024;     // 49
    int tid = threadIdx.x;
    int start = tid * CH;
    int end = start + CH; if (end > NN) end = NN;
    int sF = 0, sB = 0;
    for (int i = start; i < end; i++) { sF += g_degF[i]; sB += g_degB[i]; }
    int lane = tid & 31, wid = tid >> 5;
    int vF = sF, vB = sB;
    #pragma unroll
    for (int o = 1; o < 32; o <<= 1) {
        int tF = __shfl_up_sync(0xffffffffu, vF, o);
        int tB = __shfl_up_sync(0xffffffffu, vB, o);
        if (lane >= o) { vF += tF; vB += tB; }
    }
    if (lane == 31) { warpF[wid] = vF; warpB[wid] = vB; }
    __syncthreads();
    if (wid == 0) {
        int wF = warpF[lane], wB = warpB[lane];
        #pragma unroll
        for (int o = 1; o < 32; o <<= 1) {
            int tF = __shfl_up_sync(0xffffffffu, wF, o);
            int tB = __shfl_up_sync(0xffffffffu, wB, o);
            if (lane >= o) { wF += tF; wB += tB; }
        }
        warpF[lane] = wF; warpB[lane] = wB;
    }
    __syncthreads();
    int exF = vF - sF, exB = vB - sB;
    if (wid) { exF += warpF[wid - 1]; exB += warpB[wid - 1]; }
    int runF = exF, runB = exB;
    for (int i = start; i < end; i++) {
        g_rpF[i] = runF; runF += g_degF[i];
        g_rpB[i] = runB; runB += g_degB[i];
    }
    if (tid == 1023) { g_rpF[NN] = runF; g_rpB[NN] = runB; }
}
__global__ void k_fill(const int2* __restrict__ ei) {
    int e = blockIdx.x * 256 + threadIdx.x;
    int2 t = ei[e];
    int pf = g_rpF[t.x] + atomicAdd(&g_curF[t.x], 1);
    g_srcF[pf] = t.y; g_eidF[pf] = e;
    int pb = g_rpB[t.y] + atomicAdd(&g_curB[t.y], 1);
    g_srcB[pb] = t.x; g_eidB[pb] = e;
}

// ---------------- GEMM core: 256 thr, 64-row tile, 4x8 f32x2 per thread -----
__device__ __forceinline__ void gemm_core(
    const float* __restrict__ A, const float* __restrict__ A2,
    const float* __restrict__ B, const float* __restrict__ bias,
    const float* __restrict__ resid, float* __restrict__ C, int M, int mode,
    float* sm)
{
    float* Bs = sm;                       // 128*128 floats
    float* As = sm + U * U;               // 64*132 floats
    int tid = threadIdx.x;                // 256
    for (int i = tid; i < U * U; i += 256) Bs[i] = B[i];
    int row0 = blockIdx.x * GROWS;
    for (int i = tid; i < GROWS * 32; i += 256) {
        int r = i >> 5, c4 = i & 31;
        int rr = row0 + r;
        float4 v = {0.0f, 0.0f, 0.0f, 0.0f};
        if (rr < M) {
            v = *(const float4*)(A + (size_t)rr * U + c4 * 4);
            if (A2) {
                float4 v2 = *(const float4*)(A2 + (size_t)rr * U + c4 * 4);
                v.x += v2.x; v.y += v2.y; v.z += v2.z; v.w += v2.w;
            }
        }
        *(float4*)(As + r * ASTRIDE + c4 * 4) = v;
    }
    __syncthreads();
    int cg = tid & 15, rg = tid >> 4;
    unsigned long long acc[4][4];
    #pragma unroll
    for (int r = 0; r < 4; r++)
        #pragma unroll
        for (int j = 0; j < 4; j++) acc[r][j] = 0ull;
    const float* Bp = Bs + cg * 8;
    const float* Ap = As + rg * 4 * ASTRIDE;
    #pragma unroll 8
    for (int k = 0; k < U; k++) {
        float4 w0 = *(const float4*)(Bp + k * U);
        float4 w1 = *(const float4*)(Bp + k * U + 4);
        unsigned long long b0 = pk(w0.x, w0.y), b1 = pk(w0.z, w0.w);
        unsigned long long b2 = pk(w1.x, w1.y), b3 = pk(w1.z, w1.w);
        #pragma unroll
        for (int r = 0; r < 4; r++) {
            float a = Ap[r * ASTRIDE + k];
            unsigned long long aa = pk(a, a);
            fma2(acc[r][0], aa, b0);
            fma2(acc[r][1], aa, b1);
            fma2(acc[r][2], aa, b2);
            fma2(acc[r][3], aa, b3);
        }
    }
    float bv[8];
    #pragma unroll
    for (int j = 0; j < 8; j++) bv[j] = bias ? bias[cg * 8 + j] : 0.0f;
    #pragma unroll
    for (int r = 0; r < 4; r++) {
        int row = row0 + rg * 4 + r;
        if (row >= M) continue;
        float o[8];
        #pragma unroll
        for (int j = 0; j < 4; j++) {
            float2 f = upk(acc[r][j]);
            o[2 * j] = f.x + bv[2 * j];
            o[2 * j + 1] = f.y + bv[2 * j + 1];
        }
        if (resid) {
            float4 r0v = *(const float4*)(resid + (size_t)row * U + cg * 8);
            float4 r1v = *(const float4*)(resid + (size_t)row * U + cg * 8 + 4);
            o[0] += r0v.x; o[1] += r0v.y; o[2] += r0v.z; o[3] += r0v.w;
            o[4] += r1v.x; o[5] += r1v.y; o[6] += r1v.z; o[7] += r1v.w;
        }
        if (mode & 1) {
            #pragma unroll
            for (int j = 0; j < 8; j++) o[j] = tanhf(o[j]);
        }
        float4 s0 = {o[0], o[1], o[2], o[3]};
        float4 s1 = {o[4], o[5], o[6], o[7]};
        ((float4*)(C + (size_t)row * U + cg * 8))[0] = s0;
        ((float4*)(C + (size_t)row * U + cg * 8))[1] = s1;
    }
}

__global__ __launch_bounds__(256) void k_gemm_hn(
    const float* __restrict__ A, const float* __restrict__ B0,
    const float* __restrict__ B1, float* __restrict__ C0, float* __restrict__ C1,
    int M)
{
    extern __shared__ float sm[];
    const float* B = blockIdx.y ? B1 : B0;
    float* C = blockIdx.y ? C1 : C0;
    gemm_core(A, nullptr, B, nullptr, nullptr, C, M, 0, sm);
}

__global__ __launch_bounds__(256) void k_gemmA(
    const float* __restrict__ A, const float* __restrict__ A2,
    const float* __restrict__ B, const float* __restrict__ bias,
    const float* __restrict__ resid, float* __restrict__ C, int M, int mode,
    long yoff)
{
    extern __shared__ float sm[];
    gemm_core(A + blockIdx.y * yoff, A2, B, bias, resid, C + blockIdx.y * yoff,
              M, mode, sm);
}

// ---------------- edge score v3: warp=head GEMM + warp-per-edge epilogue ----
// Phase B: warp w computes ee columns [w*16, w*16+16) for 32 edges; weight
//   LDS are warp-uniform broadcasts (1 cyc), e-feature LDS stride-65
//   conflict-free. Only 8 u64 accumulators per thread (no spills).
// Phase C: warp w finishes edges 4w..4w+3 with coalesced hn gathers and
//   conflict-free ee_s reads; scores stored edge-major (coalesced).
__global__ __launch_bounds__(256) void k_edge_score(
    const float* __restrict__ ef,
    const int2* __restrict__ eiF, const int2* __restrict__ eiB,
    const float* __restrict__ WeF, const float* __restrict__ WeB,
    const float* __restrict__ bF, const float* __restrict__ bB,
    const float* __restrict__ attF, const float* __restrict__ attB)
{
    extern __shared__ float sm[];
    float* We_s  = sm + WE_OFF;
    float* b_s   = sm + B_OFF;
    float* att_s = sm + ATT_OFF;
    float* e_s   = sm + E_OFF;     // stride 65
    float* ee_s  = sm + EE_OFF;    // stride 132

    int bx = blockIdx.x;
    bool bwd = bx >= ESV3_HALF;
    if (bwd) bx -= ESV3_HALF;
    const int2* ei   = bwd ? eiB  : eiF;
    const float* We  = bwd ? WeB  : WeF;
    const float* bb  = bwd ? bB   : bF;
    const float* att = bwd ? attB : attF;
    const float* hn  = bwd ? g_hnB : g_hnF;
    float* scoreOut  = g_score + (bwd ? (size_t)EE * 8 : 0);

    int tid = threadIdx.x;
    for (int i = tid; i < ED * U; i += 256) We_s[i] = We[i];
    if (tid < U) { b_s[tid] = bb[tid]; att_s[tid] = att[tid]; }
    __syncthreads();

    int w = tid >> 5, lane = tid & 31;
    float4 bv = *(const float4*)(b_s + lane * 4);
    float4 av = *(const float4*)(att_s + lane * 4);

    for (int t = 0; t < NTV3; t++) {
        int e0 = (bx * NTV3 + t) * 32;
        // A: stage 32 edge-feature rows (stride 65 -> conflict-free reads)
        for (int i = tid; i < 32 * ED; i += 256) {
            int edge = i >> 6, k = i & 63;
            e_s[edge * 65 + k] = ef[(size_t)(e0 + edge) * ED + k];
        }
        __syncthreads();
        // B: ee GEMM (warp = head)
        {
            unsigned long long acc[8];
            #pragma unroll
            for (int j = 0; j < 8; j++) acc[j] = 0ull;
            const float* ep  = e_s + lane * 65;
            const float* wp0 = We_s + w * 16;
            #pragma unroll 4
            for (int k = 0; k < ED; k++) {
                float a = ep[k];
                unsigned long long aa = pk(a, a);
                const float4* wp = (const float4*)(wp0 + k * U);
                float4 w0 = wp[0], w1 = wp[1], w2 = wp[2], w3 = wp[3];
                fma2(acc[0], aa, pk(w0.x, w0.y));
                fma2(acc[1], aa, pk(w0.z, w0.w));
                fma2(acc[2], aa, pk(w1.x, w1.y));
                fma2(acc[3], aa, pk(w1.z, w1.w));
                fma2(acc[4], aa, pk(w2.x, w2.y));
                fma2(acc[5], aa, pk(w2.z, w2.w));
                fma2(acc[6], aa, pk(w3.x, w3.y));
                fma2(acc[7], aa, pk(w3.z, w3.w));
            }
            float* eo = ee_s + lane * 132 + w * 16;   // word addr 33*lane+... conflict-free
            #pragma unroll
            for (int j = 0; j < 4; j++) {
                float2 lo = upk(acc[2 * j]), hi = upk(acc[2 * j + 1]);
                float4 v = {lo.x, lo.y, hi.x, hi.y};
                *(float4*)(eo + j * 4) = v;
            }
        }
        __syncthreads();
        // C: epilogue (warp handles 4 edges; coalesced hn reads)
        #pragma unroll
        for (int s = 0; s < 4; s++) {
            int le = w * 4 + s;
            int e = e0 + le;
            int2 ts = ei[e];
            float4 eev = *(const float4*)(ee_s + le * 132 + lane * 4);
            float4 hs = *(const float4*)(hn + (size_t)ts.y * U + lane * 4);
            float4 ht = *(const float4*)(hn + (size_t)ts.x * U + lane * 4);
            float v0 = hs.x + ht.x + eev.x + bv.x;
            float v1 = hs.y + ht.y + eev.y + bv.y;
            float v2 = hs.z + ht.z + eev.z + bv.z;
            float v3 = hs.w + ht.w + eev.w + bv.w;
            v0 = fmaxf(v0, 0.2f * v0);
            v1 = fmaxf(v1, 0.2f * v1);
            v2 = fmaxf(v2, 0.2f * v2);
            v3 = fmaxf(v3, 0.2f * v3);
            float p = v0 * av.x + v1 * av.y + v2 * av.z + v3 * av.w;
            p += __shfl_xor_sync(0xffffffffu, p, 1);
            p += __shfl_xor_sync(0xffffffffu, p, 2);
            if ((lane & 3) == 0)
                scoreOut[(size_t)e * 8 + (lane >> 2)] = p;
        }
        __syncthreads();   // protect e_s/ee_s before next tile overwrites
    }
}

// ---------------- segment softmax + weighted aggregation (eid indirection) --
__device__ __forceinline__ float sel8(const float a[8], int h) {
    float r = a[0];
    r = (h == 1) ? a[1] : r; r = (h == 2) ? a[2] : r; r = (h == 3) ? a[3] : r;
    r = (h == 4) ? a[4] : r; r = (h == 5) ? a[5] : r; r = (h == 6) ? a[6] : r;
    r = (h == 7) ? a[7] : r;
    return r;
}
__global__ __launch_bounds__(256) void k_aggregate()
{
    int bx = blockIdx.x;
    bool bwd = bx >= AGG_HALF;
    if (bwd) bx -= AGG_HALF;
    const int* rowptr = bwd ? g_rpB : g_rpF;
    const int* srcarr = bwd ? g_srcB : g_srcF;
    const int* eidarr = bwd ? g_eidB : g_eidF;
    const float* hn   = bwd ? g_hnB : g_hnF;
    float* outb       = bwd ? g_gatB : g_gatF;
    const float* sco  = g_score + (bwd ? (size_t)EE * 8 : 0);

    int n = bx * 8 + (threadIdx.x >> 5);
    int lane = threadIdx.x & 31;
    if (n >= NN) return;
    int r0 = rowptr[n], r1 = rowptr[n + 1];
    int h4 = lane >> 2;
    float m[8];
    #pragma unroll
    for (int h = 0; h < 8; h++) m[h] = -3.0e38f;
    for (int i = r0 + lane; i < r1; i += 32) {
        const float4* sp = (const float4*)(sco + (size_t)eidarr[i] * 8);
        float4 a = sp[0], b = sp[1];
        m[0] = fmaxf(m[0], a.x); m[1] = fmaxf(m[1], a.y);
        m[2] = fmaxf(m[2], a.z); m[3] = fmaxf(m[3], a.w);
        m[4] = fmaxf(m[4], b.x); m[5] = fmaxf(m[5], b.y);
        m[6] = fmaxf(m[6], b.z); m[7] = fmaxf(m[7], b.w);
    }
    #pragma unroll
    for (int off = 16; off; off >>= 1)
        #pragma unroll
        for (int h = 0; h < 8; h++)
            m[h] = fmaxf(m[h], __shfl_xor_sync(0xffffffffu, m[h], off));
    float den[8];
    #pragma unroll
    for (int h = 0; h < 8; h++) den[h] = 0.0f;
    for (int i = r0 + lane; i < r1; i += 32) {
        const float4* sp = (const float4*)(sco + (size_t)eidarr[i] * 8);
        float4 a = sp[0], b = sp[1];
        den[0] += __expf(a.x - m[0]); den[1] += __expf(a.y - m[1]);
        den[2] += __expf(a.z - m[2]); den[3] += __expf(a.w - m[3]);
        den[4] += __expf(b.x - m[4]); den[5] += __expf(b.y - m[5]);
        den[6] += __expf(b.z - m[6]); den[7] += __expf(b.w - m[7]);
    }
    #pragma unroll
    for (int off = 16; off; off >>= 1)
        #pragma unroll
        for (int h = 0; h < 8; h++)
            den[h] += __shfl_xor_sync(0xffffffffu, den[h], off);
    float myinv = 1.0f / (sel8(den, h4) + 1e-9f);
    float mh = sel8(m, h4);
    float4 acc = {0.0f, 0.0f, 0.0f, 0.0f};
    int i = r0;
    for (; i + 2 <= r1; i += 2) {
        int s0 = srcarr[i], s1 = srcarr[i + 1];
        float sc0 = sco[(size_t)eidarr[i] * 8 + h4];
        float sc1 = sco[(size_t)eidarr[i + 1] * 8 + h4];
        float4 h0 = *(const float4*)(hn + (size_t)s0 * U + lane * 4);
        float4 h1 = *(const float4*)(hn + (size_t)s1 * U + lane * 4);
        float a0 = __expf(sc0 - mh) * myinv;
        float a1 = __expf(sc1 - mh) * myinv;
        acc.x += a0 * h0.x + a1 * h1.x;
        acc.y += a0 * h0.y + a1 * h1.y;
        acc.z += a0 * h0.z + a1 * h1.z;
        acc.w += a0 * h0.w + a1 * h1.w;
    }
    if (i < r1) {
        int s0 = srcarr[i];
        float sc0 = sco[(size_t)eidarr[i] * 8 + h4];
        float4 h0 = *(const float4*)(hn + (size_t)s0 * U + lane * 4);
        float a0 = __expf(sc0 - mh) * myinv;
        acc.x += a0 * h0.x; acc.y += a0 * h0.y;
        acc.z += a0 * h0.z; acc.w += a0 * h0.w;
    }
    *(float4*)(outb + (size_t)n * U + lane * 4) = acc;
}

// ---------------- dual RMS ---------------------------------------------------
__global__ __launch_bounds__(128) void k_rms_dual(
    const float* __restrict__ X, const float* __restrict__ gm,
    const float* __restrict__ fg, float* __restrict__ Yrep, float* __restrict__ Yh)
{
    __shared__ float red[4];
    int n = blockIdx.x, tid = threadIdx.x;
    float v = X[(size_t)n * U + tid];
    float s = v * v;
    #pragma unroll
    for (int off = 16; off; off >>= 1) s += __shfl_xor_sync(0xffffffffu, s, off);
    if ((tid & 31) == 0) red[tid >> 5] = s;
    __syncthreads();
    float tot = red[0] + red[1] + red[2] + red[3];
    float r1 = rsqrtf(tot * (1.0f / U) + 1e-6f);
    float rep = v * r1 * gm[tid];
    Yrep[(size_t)n * U + tid] = rep;
    if (Yh) {
        __syncthreads();
        float s2 = rep * rep;
        #pragma unroll
        for (int off = 16; off; off >>= 1) s2 += __shfl_xor_sync(0xffffffffu, s2, off);
        if ((tid & 31) == 0) red[tid >> 5] = s2;
        __syncthreads();
        float tot2 = red[0] + red[1] + red[2] + red[3];
        float r2 = rsqrtf(tot2 * (1.0f / U) + 1e-6f);
        Yh[(size_t)n * U + tid] = rep * r2 * fg[tid];
    }
}

// ---------------- depth-attention fusion ------------------------------------
__global__ __launch_bounds__(128) void k_fuse2(
    const float* __restrict__ mw, const float* __restrict__ mwb,
    const float* __restrict__ fg, float* __restrict__ out)
{
    __shared__ float red[4][NDEPTH];
    __shared__ float red2[4];
    int n = blockIdx.x, tid = threadIdx.x;
    float mwv = mw[tid];
    float z[NDEPTH], rep[NDEPTH];
    #pragma unroll
    for (int d = 0; d < NDEPTH; d++) {
        z[d] = g_z[(size_t)d * (NN * U) + (size_t)n * U + tid];
        rep[d] = g_repr[(size_t)d * (NN * U) + (size_t)n * U + tid];
    }
    #pragma unroll
    for (int d = 0; d < NDEPTH; d++) {
        float val = z[d] * mwv;
        #pragma unroll
        for (int off = 16; off; off >>= 1) val += __shfl_xor_sync(0xffffffffu, val, off);
        if ((tid & 31) == 0) red[tid >> 5][d] = val;
    }
    __syncthreads();
    float b0 = mwb[0];
    float sd[NDEPTH], mx = -1e30f;
    #pragma unroll
    for (int d = 0; d < NDEPTH; d++) {
        sd[d] = red[0][d] + red[1][d] + red[2][d] + red[3][d] + b0;
        mx = fmaxf(mx, sd[d]);
    }
    float w[NDEPTH], wsum = 0.0f;
    #pragma unroll
    for (int d = 0; d < NDEPTH; d++) { w[d] = __expf(sd[d] - mx); wsum += w[d]; }
    float inv = 1.0f / wsum;
    float fused = 0.0f;
    #pragma unroll
    for (int d = 0; d < NDEPTH; d++) fused += (w[d] * inv) * rep[d];
    float s2 = fused * fused;
    #pragma unroll
    for (int off = 16; off; off >>= 1) s2 += __shfl_xor_sync(0xffffffffu, s2, off);
    if ((tid & 31) == 0) red2[tid >> 5] = s2;
    __syncthreads();
    float tot = red2[0] + red2[1] + red2[2] + red2[3];
    out[(size_t)n * U + tid] = fused * rsqrtf(tot * (1.0f / U) + 1e-6f) * fg[tid];
}

// ---------------- host driver ----------------------------------------------
extern "C" void kernel_launch(void* const* d_in, const int* in_sizes, int n_in,
                              void* d_out, int out_size)
{
    const float* node_features = (const float*)d_in[0];
    const float* edge_features = (const float*)d_in[1];
    const int*   ei_fwd        = (const int*)d_in[2];
    const int*   ei_bwd        = (const int*)d_in[3];
    const float* Wn_f  = (const float*)d_in[4];
    const float* We_f  = (const float*)d_in[5];
    const float* b_f   = (const float*)d_in[6];
    const float* att_f = (const float*)d_in[7];
    const float* Wn_b  = (const float*)d_in[8];
    const float* We_b  = (const float*)d_in[9];
    const float* b_b   = (const float*)d_in[10];
    const float* att_b = (const float*)d_in[11];
    const float* Wo    = (const float*)d_in[12];
    const float* bo    = (const float*)d_in[13];
    const float* gamma = (const float*)d_in[14];
    const float* mo_W  = (const float*)d_in[15];
    const float* mo_b  = (const float*)d_in[16];
    const float* mow_W = (const float*)d_in[17];
    const float* mow_b = (const float*)d_in[18];
    const float* final_gamma = (const float*)d_in[19];

    float *p_h, *p_hnF, *p_hnB, *p_gatF, *p_gatB, *p_tmp, *p_repr, *p_z;
    cudaGetSymbolAddress((void**)&p_h,    g_h);
    cudaGetSymbolAddress((void**)&p_hnF,  g_hnF);
    cudaGetSymbolAddress((void**)&p_hnB,  g_hnB);
    cudaGetSymbolAddress((void**)&p_gatF, g_gatF);
    cudaGetSymbolAddress((void**)&p_gatB, g_gatB);
    cudaGetSymbolAddress((void**)&p_tmp,  g_tmp);
    cudaGetSymbolAddress((void**)&p_repr, g_repr);
    cudaGetSymbolAddress((void**)&p_z,    g_z);

    const int GEMM_SMEM = (U * U + GROWS * ASTRIDE) * (int)sizeof(float); // 99328
    cudaFuncSetAttribute(k_gemm_hn, cudaFuncAttributeMaxDynamicSharedMemorySize, GEMM_SMEM);
    cudaFuncSetAttribute(k_gemmA,   cudaFuncAttributeMaxDynamicSharedMemorySize, GEMM_SMEM);
    cudaFuncSetAttribute(k_edge_score, cudaFuncAttributeMaxDynamicSharedMemorySize, ES_SMEM_BYTES);

    const int GEMM_GRID = (NN + GROWS - 1) / GROWS;   // 782

    // Depth 0 is reordered so k_edge_score is launch idx 3 (profiled):
    // edge_score no longer needs CSR pos (edge-major stores); only fill->aggregate.
    k_count<<<EE / 256, 256>>>((const int2*)ei_fwd);                 // 0
    k_scan_both<<<1, 1024>>>();                                      // 1
    k_gemm_hn<<<dim3(GEMM_GRID, 2), 256, GEMM_SMEM>>>(               // 2
        node_features, Wn_f, Wn_b, p_hnF, p_hnB, NN);
    k_edge_score<<<2 * ESV3_HALF, 256, ES_SMEM_BYTES>>>(             // 3 <- profiled
        edge_features, (const int2*)ei_fwd, (const int2*)ei_bwd,
        We_f, We_b, b_f, b_b, att_f, att_b);
    k_fill<<<EE / 256, 256>>>((const int2*)ei_fwd);                  // 4
    k_aggregate<<<2 * AGG_HALF, 256>>>();                            // 5

    const float* hcur = node_features;
    for (int i = 0; i < NDEPTH; i++) {
        if (i > 0) {
            k_gemm_hn<<<dim3(GEMM_GRID, 2), 256, GEMM_SMEM>>>(
                hcur, Wn_f + i * U * U, Wn_b + i * U * U, p_hnF, p_hnB, NN);
            k_edge_score<<<2 * ESV3_HALF, 256, ES_SMEM_BYTES>>>(
                edge_features, (const int2*)ei_fwd, (const int2*)ei_bwd,
                We_f + i * ED * U, We_b + i * ED * U, b_f + i * U, b_b + i * U,
                att_f + i * U, att_b + i * U);
            k_aggregate<<<2 * AGG_HALF, 256>>>();
        }
        k_gemmA<<<dim3(GEMM_GRID, 1), 256, GEMM_SMEM>>>(
            p_gatF, p_gatB, Wo + i * U * U, bo + i * U, hcur, p_tmp, NN, 0, 0L);
        k_rms_dual<<<NN, 128>>>(p_tmp, gamma + i * U, final_gamma,
                                p_repr + (size_t)i * NN * U,
                                (i < NDEPTH - 1) ? p_h : nullptr);
        hcur = p_h;
    }

    k_gemmA<<<dim3(GEMM_GRID, NDEPTH), 256, GEMM_SMEM>>>(
        p_repr, nullptr, mo_W, mo_b, nullptr, p_z, NN, 1, (long)NN * U);
    k_fuse2<<<NN, 128>>>(mow_W, mow_b, final_gamma, (float*)d_out);

    // restore deg/cur = 0 invariant for the next call / graph replay
    k_zero_counts<<<NBLK, 256>>>();
}